// round 13
// baseline (speedup 1.0000x reference)
#include <cuda_runtime.h>
#include <cuda_fp16.h>
#include <cstdint>

#define T_DIM 4
#define B_DIM 64
#define C_DIM 256
#define N_DIM 256
#define HEADS 8
#define TAU 0.5f
#define THRESH 1.0f
#define ATTN_THRESH 0.5f
#define BN_EPS 1e-5f
#define OROWS 512
#define TB_TOT (T_DIM * B_DIM)
#define LO_SCALE 0.00048828125f   // 2^-11, exact power of two

#define SW128(b) ((b) ^ (((b) >> 3) & 0x70))

// ---------------- scratch ----------------
__device__ __align__(16) __half g_s[TB_TOT * N_DIM * 512];     // [tb][n][2c|2c+1] spike hi/lo
__device__ __align__(16) __half g_qk[TB_TOT * N_DIM * OROWS];  // q/k spikes (tb,n,o) fp16
__device__ __align__(16) __half g_y[TB_TOT * N_DIM * C_DIM];   // y = attn*k (tb,n,c) fp16
__device__ __align__(16) __half g_w1[OROWS * 512];             // [o][hi,lo interleaved]
__device__ __align__(16) __half g_w2h[C_DIM * C_DIM];          // [o][c] fp16(w2)
__device__ float g_inv[OROWS], g_add[OROWS];
__device__ float g_inv2[C_DIM], g_add2[C_DIM];

// ---------------- PTX helpers ----------------
__device__ __forceinline__ uint32_t smem_u32(const void* p) {
    uint32_t a;
    asm("{ .reg .u64 t; cvta.to.shared.u64 t, %1; cvt.u32.u64 %0, t; }" : "=r"(a) : "l"(p));
    return a;
}
__device__ __forceinline__ void ldmx4(uint32_t* r, uint32_t addr) {
    asm volatile("ldmatrix.sync.aligned.m8n8.x4.shared.b16 {%0,%1,%2,%3}, [%4];"
        : "=r"(r[0]), "=r"(r[1]), "=r"(r[2]), "=r"(r[3]) : "r"(addr));
}
__device__ __forceinline__ void mma16816(float* c, const uint32_t* a, uint32_t b0, uint32_t b1) {
    asm volatile("mma.sync.aligned.m16n8k16.row.col.f32.f16.f16.f32 "
        "{%0,%1,%2,%3}, {%4,%5,%6,%7}, {%8,%9}, {%0,%1,%2,%3};"
        : "+f"(c[0]), "+f"(c[1]), "+f"(c[2]), "+f"(c[3])
        : "r"(a[0]), "r"(a[1]), "r"(a[2]), "r"(a[3]), "r"(b0), "r"(b1));
}
__device__ __forceinline__ void cpa16(uint32_t dst, const void* src) {
    asm volatile("cp.async.cg.shared.global [%0], [%1], 16;" :: "r"(dst), "l"(src));
}
#define CPA_COMMIT() asm volatile("cp.async.commit_group;" ::: "memory")
#define CPA_WAIT(n)  asm volatile("cp.async.wait_group %0;" :: "n"(n) : "memory")

// ---------------- K0: weight prep + BN ----------------
__global__ void k0_prep(const float* __restrict__ wq, const float* __restrict__ wk,
                        const float* __restrict__ wp, const float* __restrict__ pb,
                        const float* __restrict__ qg, const float* __restrict__ qb,
                        const float* __restrict__ qm, const float* __restrict__ qv,
                        const float* __restrict__ kg, const float* __restrict__ kb,
                        const float* __restrict__ km, const float* __restrict__ kv,
                        const float* __restrict__ pg, const float* __restrict__ pbeta,
                        const float* __restrict__ pm, const float* __restrict__ pv) {
    int r = blockIdx.x;   // 0..767
    int c = threadIdx.x;  // 0..255
    if (r < OROWS) {
        float w = (r < C_DIM) ? wq[r * C_DIM + c] : wk[(r - C_DIM) * C_DIM + c];
        __half hi = __float2half_rn(w);
        float lo = (w - __half2float(hi)) * 2048.f;
        g_w1[r * 512 + 2 * c] = hi;
        g_w1[r * 512 + 2 * c + 1] = __float2half_rn(lo);
        if (c == 0) {
            float iv, ad;
            if (r < C_DIM) { iv = qg[r] * rsqrtf(qv[r] + BN_EPS); ad = qb[r] - qm[r] * iv; }
            else { int o = r - C_DIM; iv = kg[o] * rsqrtf(kv[o] + BN_EPS); ad = kb[o] - km[o] * iv; }
            g_inv[r] = iv; g_add[r] = ad;
        }
    } else {
        int o = r - OROWS;
        g_w2h[o * C_DIM + c] = __float2half_rn(wp[o * C_DIM + c]);
        if (c == 0) {
            float iv = pg[o] * rsqrtf(pv[o] + BN_EPS);
            g_inv2[o] = iv;
            g_add2[o] = pb[o] * iv + pbeta[o] - pm[o] * iv;
        }
    }
}

// ---------------- K1: input LIF + transpose -> g_s ----------------
__global__ __launch_bounds__(1024) void k1_lif_input(const float* __restrict__ x) {
    __shared__ float tile[T_DIM][32][33];
    const int n0 = blockIdx.x * 32, c0 = blockIdx.y * 32, b = blockIdx.z;
    const int tid = threadIdx.x;
    const int cl = tid >> 5, nl = tid & 31;
    const int cl2 = tid & 31, nl2 = tid >> 5;
    float mem = 0.f;
#pragma unroll
    for (int t = 0; t < T_DIM; t++) {
        int tb = t * B_DIM + b;
        float v = x[((size_t)tb * C_DIM + c0 + cl) * N_DIM + n0 + nl];
        mem = mem * TAU + v;
        float sp = (mem >= THRESH) ? 1.f : 0.f;
        mem *= (1.f - sp);
        tile[t][cl][nl] = sp;
    }
    __syncthreads();
#pragma unroll
    for (int t = 0; t < T_DIM; t++) {
        int tb = t * B_DIM + b;
        float s2 = tile[t][cl2][nl2];
        size_t base = ((size_t)tb * N_DIM + n0 + nl2) * 512 + 2 * (c0 + cl2);
        *reinterpret_cast<__half2*>(g_s + base) = __floats2half2_rn(s2, s2 * LO_SCALE);
    }
}

// ---------------- G1F: fused GEMM + BN + LIF over t -> q/k spikes ----------------
// grid (4 mtiles x128 o, 4 ntiles x64 n, 64 b); 256 thr = 8 warps (4m x 2n), warp 32x32.
// smem: A 2x16K @0 | B 2x8K @32K ; epilogue stage (128x66 fp16) overlays A region.
#define STP 66
__global__ __launch_bounds__(256) void g1_fused() {
    extern __shared__ char sm[];
    __half* stage = reinterpret_cast<__half*>(sm);
    const uint32_t sb = smem_u32(sm);

    const int mtile = blockIdx.x, ntile = blockIdx.y, b = blockIdx.z;
    const int tid = threadIdx.x, wid = tid >> 5, lane = tid & 31;
    const int warp_m = wid >> 1, warp_n = wid & 1;

    const int a_row = warp_m * 32 + (lane & 7) + ((lane >> 3) & 1) * 8;
    const int a_kadd = (lane >> 4) * 8;
    const int b_row = warp_n * 32 + (lane & 7) + (lane >> 4) * 8;
    const int b_kadd = ((lane >> 3) & 1) * 8;

    float ivs[2][2], ads[2][2];
#pragma unroll
    for (int mb = 0; mb < 2; mb++)
#pragma unroll
        for (int g = 0; g < 2; g++) {
            int o = mtile * 128 + warp_m * 32 + mb * 16 + g * 8 + (lane >> 2);
            ivs[mb][g] = g_inv[o];
            ads[mb][g] = g_add[o];
        }

    float mem[2][4][4];
#pragma unroll
    for (int i = 0; i < 2; i++)
#pragma unroll
        for (int j = 0; j < 4; j++)
#pragma unroll
            for (int q = 0; q < 4; q++) mem[i][j][q] = 0.f;

    const __half* Ag = g_w1 + (size_t)(mtile * 128) * 512;

    for (int t = 0; t < T_DIM; t++) {
        const int tb = t * B_DIM + b;
        const __half* Bg = g_s + ((size_t)tb * N_DIM + ntile * 64) * 512;

        float acc[2][4][4];
#pragma unroll
        for (int i = 0; i < 2; i++)
#pragma unroll
            for (int j = 0; j < 4; j++)
#pragma unroll
                for (int q = 0; q < 4; q++) acc[i][j][q] = 0.f;

        // prefetch chunk 0 (A 16KB: 4x, B 8KB: 2x)
#pragma unroll
        for (int i = 0; i < 4; i++) {
            int idx = tid + i * 256, row = idx >> 3, c16 = idx & 7;
            cpa16(sb + SW128(row * 128 + c16 * 16), Ag + row * 512 + c16 * 8);
        }
#pragma unroll
        for (int i = 0; i < 2; i++) {
            int idx = tid + i * 256, row = idx >> 3, c16 = idx & 7;
            cpa16(sb + 32768u + SW128(row * 128 + c16 * 16), Bg + row * 512 + c16 * 8);
        }
        CPA_COMMIT();

        for (int ch = 0; ch < 8; ch++) {
            const uint32_t bufA = sb + (uint32_t)(ch & 1) * 16384u;
            const uint32_t bufB = sb + 32768u + (uint32_t)(ch & 1) * 8192u;
            if (ch < 7) {
                const int kc = (ch + 1) * 64;
                const uint32_t nA = sb + (uint32_t)((ch + 1) & 1) * 16384u;
                const uint32_t nB = sb + 32768u + (uint32_t)((ch + 1) & 1) * 8192u;
#pragma unroll
                for (int i = 0; i < 4; i++) {
                    int idx = tid + i * 256, row = idx >> 3, c16 = idx & 7;
                    cpa16(nA + SW128(row * 128 + c16 * 16), Ag + row * 512 + kc + c16 * 8);
                }
#pragma unroll
                for (int i = 0; i < 2; i++) {
                    int idx = tid + i * 256, row = idx >> 3, c16 = idx & 7;
                    cpa16(nB + SW128(row * 128 + c16 * 16), Bg + row * 512 + kc + c16 * 8);
                }
                CPA_COMMIT();
                CPA_WAIT(1);
            } else {
                CPA_WAIT(0);
            }
            __syncthreads();
#pragma unroll
            for (int k16 = 0; k16 < 4; k16++) {
                uint32_t afr[2][4], bfr[2][4];
#pragma unroll
                for (int mb = 0; mb < 2; mb++)
                    ldmx4(afr[mb], bufA + SW128((a_row + mb * 16) * 128 + (k16 * 16 + a_kadd) * 2));
#pragma unroll
                for (int p = 0; p < 2; p++)
                    ldmx4(bfr[p], bufB + SW128((b_row + p * 16) * 128 + (k16 * 16 + b_kadd) * 2));
#pragma unroll
                for (int mb = 0; mb < 2; mb++)
#pragma unroll
                    for (int p = 0; p < 2; p++) {
                        mma16816(acc[mb][2 * p], afr[mb], bfr[p][0], bfr[p][1]);
                        mma16816(acc[mb][2 * p + 1], afr[mb], bfr[p][2], bfr[p][3]);
                    }
            }
            __syncthreads();
        }

        // epilogue: BN + LIF (membrane persists over t) -> stage fp16 spikes
#pragma unroll
        for (int mb = 0; mb < 2; mb++)
#pragma unroll
            for (int nb = 0; nb < 4; nb++) {
                int o_l = warp_m * 32 + mb * 16 + (lane >> 2);
                int nn = warp_n * 32 + nb * 8 + (lane & 3) * 2;
#pragma unroll
                for (int q = 0; q < 4; q++) {
                    int g = q >> 1;
                    float v = acc[mb][nb][q] * ivs[mb][g] + ads[mb][g];
                    float m = mem[mb][nb][q] * TAU + v;
                    float sp = (m >= THRESH) ? 1.f : 0.f;
                    mem[mb][nb][q] = m * (1.f - sp);
                    stage[(o_l + g * 8) * STP + nn + (q & 1)] = __float2half_rn(sp);
                }
            }
        __syncthreads();
        // store: thread n_l = tid>>2 (0..63), seg = tid&3 -> 32 o's = 4 uint4
        {
            int n_l = tid >> 2, seg = tid & 3;
            __half* dst = g_qk + ((size_t)tb * N_DIM + ntile * 64 + n_l) * OROWS
                               + mtile * 128 + seg * 32;
#pragma unroll
            for (int v4 = 0; v4 < 4; v4++) {
                uint4 o4;
                __half* hp = reinterpret_cast<__half*>(&o4);
#pragma unroll
                for (int j = 0; j < 8; j++)
                    hp[j] = stage[(seg * 32 + v4 * 8 + j) * STP + n_l];
                *reinterpret_cast<uint4*>(dst + v4 * 8) = o4;
            }
        }
        __syncthreads();
    }
}

// ---------------- K23': head sums + decay memory + attn LIF -> y fp16 ----------------
// one warp per (b,n); lane owns 8 q-channels [8l..8l+7] and 8 k-channels (head = l>>2)
__global__ __launch_bounds__(256) void k23_attn(const float* __restrict__ alpha_p) {
    const int gw = blockIdx.x * 8 + (threadIdx.x >> 5);
    const int lane = threadIdx.x & 31;
    const int b = gw >> 8, n = gw & 255;
    const float a = *alpha_p;

    float M = 0.f, amem = 0.f;   // per-head (head = lane>>2), replicated across 4 lanes
#pragma unroll
    for (int t = 0; t < T_DIM; t++) {
        const int tb = t * B_DIM + b;
        const __half* row = g_qk + ((size_t)tb * N_DIM + n) * OROWS;
        uint4 qv = *reinterpret_cast<const uint4*>(row + 8 * lane);
        uint4 kv = *reinterpret_cast<const uint4*>(row + 256 + 8 * lane);
        const __half2* q2 = reinterpret_cast<const __half2*>(&qv);
        float Q = 0.f;
#pragma unroll
        for (int j = 0; j < 4; j++) {
            float2 f = __half22float2(q2[j]);
            Q += f.x + f.y;
        }
        Q += __shfl_xor_sync(0xffffffffu, Q, 1, 4);
        Q += __shfl_xor_sync(0xffffffffu, Q, 2, 4);

        M = (1.f - a) * M + a * Q;
        float qs = M + Q;
        amem = amem * TAU + qs;
        float sp = (amem >= ATTN_THRESH) ? 1.f : 0.f;
        amem *= (1.f - sp);

        // y = attn * k for this lane's 8 channels
        __half2 s2 = __floats2half2_rn(sp, sp);
        uint4 ov;
        __half2* kp = reinterpret_cast<__half2*>(&kv);
        __half2* op = reinterpret_cast<__half2*>(&ov);
#pragma unroll
        for (int j = 0; j < 4; j++) op[j] = __hmul2(kp[j], s2);
        *reinterpret_cast<uint4*>(g_y + ((size_t)tb * N_DIM + n) * C_DIM + 8 * lane) = ov;
    }
}

// ---------------- G2: GEMM out = BN(W2h @ y + bias), 2-stage  M=256 N=256 K=256 ----------------
__global__ __launch_bounds__(256) void g2_gemm(float* __restrict__ out) {
    extern __shared__ char sm[];
    const uint32_t sb = smem_u32(sm);

    const int mtile = blockIdx.x, ntile = blockIdx.y, tb = blockIdx.z;
    const int tid = threadIdx.x, wid = tid >> 5, lane = tid & 31;
    const int warp_m = wid >> 1, warp_n = wid & 1;

    float acc[2][8][4];
#pragma unroll
    for (int i = 0; i < 2; i++)
#pragma unroll
        for (int j = 0; j < 8; j++)
#pragma unroll
            for (int q = 0; q < 4; q++) acc[i][j][q] = 0.f;

    const int a_row = warp_m * 32 + (lane & 7) + ((lane >> 3) & 1) * 8;
    const int a_kadd = (lane >> 4) * 8;
    const int b_row = warp_n * 64 + (lane & 7) + (lane >> 4) * 8;
    const int b_kadd = ((lane >> 3) & 1) * 8;

    const __half* Ag = g_w2h + (size_t)(mtile * 128) * C_DIM;
    const __half* Bg = g_y + ((size_t)tb * N_DIM + ntile * 128) * C_DIM;

#pragma unroll
    for (int i = 0; i < 4; i++) {
        int idx = tid + i * 256, row = idx >> 3, c16 = idx & 7;
        cpa16(sb + SW128(row * 128 + c16 * 16), Ag + row * C_DIM + c16 * 8);
        cpa16(sb + 32768u + SW128(row * 128 + c16 * 16), Bg + row * C_DIM + c16 * 8);
    }
    CPA_COMMIT();

    for (int ch = 0; ch < 4; ch++) {
        const uint32_t bufA = sb + (uint32_t)(ch & 1) * 16384u;
        const uint32_t bufB = sb + 32768u + (uint32_t)(ch & 1) * 16384u;
        if (ch < 3) {
            const int kc = (ch + 1) * 64;
            const uint32_t nA = sb + (uint32_t)((ch + 1) & 1) * 16384u;
            const uint32_t nB = sb + 32768u + (uint32_t)((ch + 1) & 1) * 16384u;
#pragma unroll
            for (int i = 0; i < 4; i++) {
                int idx = tid + i * 256, row = idx >> 3, c16 = idx & 7;
                cpa16(nA + SW128(row * 128 + c16 * 16), Ag + row * C_DIM + kc + c16 * 8);
                cpa16(nB + SW128(row * 128 + c16 * 16), Bg + row * C_DIM + kc + c16 * 8);
            }
            CPA_COMMIT();
            CPA_WAIT(1);
        } else {
            CPA_WAIT(0);
        }
        __syncthreads();
#pragma unroll
        for (int k16 = 0; k16 < 4; k16++) {
            uint32_t afr[2][4], bfr[4][4];
#pragma unroll
            for (int mb = 0; mb < 2; mb++)
                ldmx4(afr[mb], bufA + SW128((a_row + mb * 16) * 128 + (k16 * 16 + a_kadd) * 2));
#pragma unroll
            for (int p = 0; p < 4; p++)
                ldmx4(bfr[p], bufB + SW128((b_row + p * 16) * 128 + (k16 * 16 + b_kadd) * 2));
#pragma unroll
            for (int mb = 0; mb < 2; mb++)
#pragma unroll
                for (int p = 0; p < 4; p++) {
                    mma16816(acc[mb][2 * p], afr[mb], bfr[p][0], bfr[p][1]);
                    mma16816(acc[mb][2 * p + 1], afr[mb], bfr[p][2], bfr[p][3]);
                }
        }
        __syncthreads();
    }

#pragma unroll
    for (int mb = 0; mb < 2; mb++) {
        int o0 = mtile * 128 + warp_m * 32 + mb * 16 + (lane >> 2);
        float iva = g_inv2[o0], ada = g_add2[o0];
        float ivb = g_inv2[o0 + 8], adb = g_add2[o0 + 8];
#pragma unroll
        for (int nb = 0; nb < 8; nb++) {
            int n_g = ntile * 128 + warp_n * 64 + nb * 8 + (lane & 3) * 2;
            float2 v0 = make_float2(acc[mb][nb][0] * iva + ada, acc[mb][nb][1] * iva + ada);
            float2 v1 = make_float2(acc[mb][nb][2] * ivb + adb, acc[mb][nb][3] * ivb + adb);
            *reinterpret_cast<float2*>(out + ((size_t)tb * C_DIM + o0) * N_DIM + n_g) = v0;
            *reinterpret_cast<float2*>(out + ((size_t)tb * C_DIM + o0 + 8) * N_DIM + n_g) = v1;
        }
    }
}

// ---------------- launch ----------------
extern "C" void kernel_launch(void* const* d_in, const int* in_sizes, int n_in,
                              void* d_out, int out_size) {
    const float* x       = (const float*)d_in[0];
    const float* q_w     = (const float*)d_in[1];
    const float* q_gamma = (const float*)d_in[2];
    const float* q_beta  = (const float*)d_in[3];
    const float* q_mean  = (const float*)d_in[4];
    const float* q_var   = (const float*)d_in[5];
    const float* k_w     = (const float*)d_in[6];
    const float* k_gamma = (const float*)d_in[7];
    const float* k_beta  = (const float*)d_in[8];
    const float* k_mean  = (const float*)d_in[9];
    const float* k_var   = (const float*)d_in[10];
    const float* proj_w  = (const float*)d_in[11];
    const float* proj_b  = (const float*)d_in[12];
    const float* proj_g  = (const float*)d_in[13];
    const float* proj_be = (const float*)d_in[14];
    const float* proj_m  = (const float*)d_in[15];
    const float* proj_v  = (const float*)d_in[16];
    const float* alpha   = (const float*)d_in[17];
    float* out = (float*)d_out;

    cudaFuncSetAttribute(g1_fused, cudaFuncAttributeMaxDynamicSharedMemorySize, 49152);
    cudaFuncSetAttribute(g2_gemm, cudaFuncAttributeMaxDynamicSharedMemorySize, 65536);

    k0_prep<<<OROWS + C_DIM, 256>>>(q_w, k_w, proj_w, proj_b,
                                    q_gamma, q_beta, q_mean, q_var,
                                    k_gamma, k_beta, k_mean, k_var,
                                    proj_g, proj_be, proj_m, proj_v);
    {
        dim3 grid(N_DIM / 32, C_DIM / 32, B_DIM);
        k1_lif_input<<<grid, 1024>>>(x);
    }
    {
        dim3 grid(4, 4, B_DIM);
        g1_fused<<<grid, 256, 49152>>>();
    }
    {
        k23_attn<<<B_DIM * N_DIM / 8, 256>>>(alpha);
    }
    {
        dim3 grid(2, 2, TB_TOT);
        g2_gemm<<<grid, 256, 65536>>>(out);
    }
}